// round 7
// baseline (speedup 1.0000x reference)
#include <cuda_runtime.h>
#include <math.h>

// ---------------------------------------------------------------------------
// GRU T=512 B=64 IC=HC=512 L=2.
//   A1 = in @ W1x^T + b1  (parallel GEMM, 2*HC cols)
//   A2 = in @ W2x^T + b2  (parallel GEMM, HC cols)
//   per step: pre1 = A1[t] + h @ W1h^T ; r,z = sigmoid
//             pre2 = A2[t] + (r*h) @ W2h^T ; g = tanh ; h = z*h + (1-z)*g
// Recurrence fused into ONE persistent kernel per layer (128 CTAs, grid
// barrier) so the captured graph has only 8 nodes (fixes the 4MB graph-upload
// teardown violation seen with ~3080 nodes) and weights stay SMEM-resident.
// ---------------------------------------------------------------------------

#define TSTEPS 512
#define BATCH  64
#define HC     512
#define NLAYER 2
#define W1ROWS 1024
#define WLD    1024
#define NCTA   128

// Scratch (no allocations allowed anywhere)
__device__ float g_A1 [TSTEPS * BATCH * W1ROWS];  // input half of pre1
__device__ float g_A2 [TSTEPS * BATCH * HC];      // input half of pre2
__device__ float g_h1s[TSTEPS * BATCH * HC];      // layer-1 output sequence
__device__ float g_hT [HC * BATCH];               // h,  packed [(k>>2)*64+b]*4+(k&3)
__device__ float g_rhT[HC * BATCH];               // r*h, same packing
__device__ float g_zT [HC * BATCH];               // z, [j*64 + b]
__device__ unsigned          g_arrive;
__device__ volatile unsigned g_gen;

// ---------------------------------------------------------------------------
// Grid barrier: monotonic arrive counter + generation flag. All 128 CTAs are
// co-resident (<=148 SMs, 32KB smem, 256 thr) so spinning is deadlock-free.
// n = barrier index (same on every CTA, statically determined).
// ---------------------------------------------------------------------------
__device__ __forceinline__ void grid_barrier(unsigned n) {
    __syncthreads();
    if (threadIdx.x == 0) {
        __threadfence();
        unsigned a = atomicAdd(&g_arrive, 1u);
        if (a == n * NCTA + (NCTA - 1)) {
            atomicExch((unsigned*)&g_gen, n + 1u);
        } else {
            while (g_gen < n + 1u) { }
        }
        __threadfence();
    }
    __syncthreads();
}

// ---------------------------------------------------------------------------
// Input GEMM: C[n,j] = bias[j] + sum_{k<512} X[n,k]*W[j,k]
// X [M,512] row-major, W [N,WLD] row-major (first 512 cols), BM=BN=64 BK=16.
// ---------------------------------------------------------------------------
__global__ __launch_bounds__(256) void input_gemm_kernel(
    const float* __restrict__ X, const float* __restrict__ W,
    const float* __restrict__ bias, float* __restrict__ C, int N)
{
    __shared__ float As[16][68];
    __shared__ float Bs[16][68];
    const int n0 = blockIdx.y * 64, j0 = blockIdx.x * 64;
    const int tid = threadIdx.x;
    const int tx = tid & 15, ty = tid >> 4;
    const int lr = tid >> 2, lq = tid & 3;

    const float* Xp = X + (size_t)(n0 + lr) * 512 + lq * 4;
    const float* Wp = W + (size_t)(j0 + lr) * WLD + lq * 4;

    float acc[4][4];
    #pragma unroll
    for (int u = 0; u < 4; u++)
        #pragma unroll
        for (int v = 0; v < 4; v++) acc[u][v] = 0.f;

    for (int k0 = 0; k0 < 512; k0 += 16) {
        float4 av = *(const float4*)(Xp + k0);
        float4 bv = *(const float4*)(Wp + k0);
        As[lq*4+0][lr] = av.x; As[lq*4+1][lr] = av.y;
        As[lq*4+2][lr] = av.z; As[lq*4+3][lr] = av.w;
        Bs[lq*4+0][lr] = bv.x; Bs[lq*4+1][lr] = bv.y;
        Bs[lq*4+2][lr] = bv.z; Bs[lq*4+3][lr] = bv.w;
        __syncthreads();
        #pragma unroll
        for (int kk = 0; kk < 16; kk++) {
            float a[4], b[4];
            #pragma unroll
            for (int u = 0; u < 4; u++) a[u] = As[kk][ty*4 + u];
            #pragma unroll
            for (int v = 0; v < 4; v++) b[v] = Bs[kk][tx*4 + v];
            #pragma unroll
            for (int u = 0; u < 4; u++)
                #pragma unroll
                for (int v = 0; v < 4; v++) acc[u][v] += a[u] * b[v];
        }
        __syncthreads();
    }
    const float4 bb = *(const float4*)(bias + j0 + tx*4);
    #pragma unroll
    for (int u = 0; u < 4; u++) {
        float4 o;
        o.x = acc[u][0] + bb.x; o.y = acc[u][1] + bb.y;
        o.z = acc[u][2] + bb.z; o.w = acc[u][3] + bb.w;
        *(float4*)(C + (size_t)(n0 + ty*4 + u) * N + j0 + tx*4) = o;
    }
}

// Per-layer init: broadcast h0 into packed hT, reset barrier state.
__global__ __launch_bounds__(256) void layer_init_kernel(const float* __restrict__ hid)
{
    const int i = blockIdx.x * 256 + threadIdx.x;      // grid covers 64*512
    const int b = i & 63, k = i >> 6;
    g_hT[((k >> 2) * 64 + b) * 4 + (k & 3)] = hid[k];
    if (i == 0) { g_arrive = 0u; *(unsigned*)&g_gen = 0u; }
}

// ---------------------------------------------------------------------------
// Persistent recurrent kernel. CTA c owns:
//   phase A: gate columns jg = c*8 .. c*8+7   (c<64 -> r cols, c>=64 -> z cols)
//   phase B: g columns   j  = c*4 .. c*4+3
// Warp w: b-half = w>>2, k-quarter = w&3, lane = local batch index.
// Weights cached in SMEM once for the whole layer.
// ---------------------------------------------------------------------------
__global__ __launch_bounds__(256, 1) void gru_persist(
    const float* __restrict__ W1L, const float* __restrict__ W2L,
    const float* __restrict__ A1,  const float* __restrict__ A2,
    float* __restrict__ seq, float* __restrict__ hfin)
{
    __shared__ float WA[8 * 512];     // [jl*512 + k]  (hidden half of W1 rows)
    __shared__ float WB[4 * 512];
    __shared__ float red[8 * 32 * 8]; // [warp*32+lane][jl]

    const int c = blockIdx.x, tid = threadIdx.x;
    const int w = tid >> 5, lane = tid & 31;
    const int bh = w >> 2, kq = w & 3;
    const int b  = bh * 32 + lane;
    const int k40 = kq * 32;          // 32 float4 k-groups per quarter

    for (int i = tid; i < 8 * 512; i += 256)
        WA[i] = W1L[(size_t)(c * 8 + (i >> 9)) * WLD + 512 + (i & 511)];
    for (int i = tid; i < 4 * 512; i += 256)
        WB[i] = W2L[(size_t)(c * 4 + (i >> 9)) * WLD + 512 + (i & 511)];
    __syncthreads();

    const float4* hT4  = (const float4*)g_hT;
    const float4* rhT4 = (const float4*)g_rhT;
    const float4* WA4  = (const float4*)WA;
    const float4* WB4  = (const float4*)WB;

    // combine-phase mapping
    const int b2  = tid >> 2;
    const int j0A = (tid & 3) * 2;    // phase A: 2 outputs
    const int jlB = tid & 3;          // phase B: 1 output
    const int jgA0 = c * 8 + j0A;     // absolute gate cols for phase A outputs
    const int jB   = c * 4 + jlB;     // absolute g col for phase B output

    for (int t = 0; t < TSTEPS; t++) {
        // =================== phase A: pre1 -> r,z ===================
        // prefetch A1 / old-h values used in the combine step
        const float a10 = A1[((size_t)t * 64 + b2) * 1024 + jgA0];
        const float a11 = A1[((size_t)t * 64 + b2) * 1024 + jgA0 + 1];
        float hb0 = 0.f, hb1 = 0.f;
        if (c < 64) {
            hb0 = __ldcg(&g_hT[((jgA0 >> 2) * 64 + b2) * 4 + (jgA0 & 3)]);
            hb1 = __ldcg(&g_hT[(((jgA0 + 1) >> 2) * 64 + b2) * 4 + ((jgA0 + 1) & 3)]);
        }
        {
            float acc[8];
            #pragma unroll
            for (int jl = 0; jl < 8; jl++) acc[jl] = 0.f;
            const float4* hp = hT4 + (size_t)k40 * 64 + b;
            float4 hv = __ldcg(hp);
            #pragma unroll 4
            for (int i = 0; i < 32; i++) {
                float4 hn = hv;
                if (i != 31) hn = __ldcg(hp + (size_t)(i + 1) * 64);
                const int k4 = k40 + i;
                #pragma unroll
                for (int jl = 0; jl < 8; jl++) {
                    float4 wv = WA4[jl * 128 + k4];
                    acc[jl] = fmaf(hv.x, wv.x, fmaf(hv.y, wv.y,
                              fmaf(hv.z, wv.z, fmaf(hv.w, wv.w, acc[jl]))));
                }
                hv = hn;
            }
            float* rp = &red[(w * 32 + lane) * 8];
            #pragma unroll
            for (int jl = 0; jl < 8; jl++) rp[jl] = acc[jl];
        }
        __syncthreads();
        {
            const int bhh = b2 >> 5, bl = b2 & 31;
            #pragma unroll
            for (int u = 0; u < 2; u++) {
                float s = 0.f;
                #pragma unroll
                for (int q = 0; q < 4; q++)
                    s += red[((bhh * 4 + q) * 32 + bl) * 8 + j0A + u];
                const float pre = s + (u ? a11 : a10);
                const float sg = 1.f / (1.f + __expf(-pre));
                const int jg = jgA0 + u;
                if (c < 64) {   // r gate -> write r*h (packed)
                    g_rhT[((jg >> 2) * 64 + b2) * 4 + (jg & 3)] = sg * (u ? hb1 : hb0);
                } else {        // z gate -> write zT
                    g_zT[(jg - 512) * 64 + b2] = sg;
                }
            }
        }
        grid_barrier(2u * t);

        // =================== phase B: pre2 -> g -> h ===================
        const float a2v  = A2[((size_t)t * 64 + b2) * 512 + jB];
        const float zv   = __ldcg(&g_zT[jB * 64 + b2]);
        const float hold = __ldcg(&g_hT[((jB >> 2) * 64 + b2) * 4 + (jB & 3)]);
        {
            float acc[4];
            #pragma unroll
            for (int jl = 0; jl < 4; jl++) acc[jl] = 0.f;
            const float4* rp4 = rhT4 + (size_t)k40 * 64 + b;
            float4 rv = __ldcg(rp4);
            #pragma unroll 4
            for (int i = 0; i < 32; i++) {
                float4 rn = rv;
                if (i != 31) rn = __ldcg(rp4 + (size_t)(i + 1) * 64);
                const int k4 = k40 + i;
                #pragma unroll
                for (int jl = 0; jl < 4; jl++) {
                    float4 wv = WB4[jl * 128 + k4];
                    acc[jl] = fmaf(rv.x, wv.x, fmaf(rv.y, wv.y,
                              fmaf(rv.z, wv.z, fmaf(rv.w, wv.w, acc[jl]))));
                }
                rv = rn;
            }
            float* rp = &red[(w * 32 + lane) * 4];
            #pragma unroll
            for (int jl = 0; jl < 4; jl++) rp[jl] = acc[jl];
        }
        __syncthreads();
        {
            const int bhh = b2 >> 5, bl = b2 & 31;
            float s = 0.f;
            #pragma unroll
            for (int q = 0; q < 4; q++)
                s += red[((bhh * 4 + q) * 32 + bl) * 4 + jlB];
            const float g  = tanhf(s + a2v);
            const float hn = zv * hold + (1.f - zv) * g;
            g_hT[((jB >> 2) * 64 + b2) * 4 + (jB & 3)] = hn;
            seq[((size_t)t * 64 + b2) * 512 + jB] = hn;
            if (t == TSTEPS - 1) hfin[b2 * 512 + jB] = hn;
        }
        grid_barrier(2u * t + 1u);
    }
}

// ---------------------------------------------------------------------------
// Inputs: x[512,64,512], hiddens[2,1,512], W1[2,1024,1024], b1[2,1024],
//         W2[2,512,1024], b2[2,512]
// Output: out_seq[512,64,512] ++ hs[2,64,512]
// ---------------------------------------------------------------------------
extern "C" void kernel_launch(void* const* d_in, const int* in_sizes, int n_in,
                              void* d_out, int out_size)
{
    const float* x   = (const float*)d_in[0];
    const float* hid = (const float*)d_in[1];
    const float* W1  = (const float*)d_in[2];
    const float* b1  = (const float*)d_in[3];
    const float* W2  = (const float*)d_in[4];
    const float* b2  = (const float*)d_in[5];

    float* out_seq = (float*)d_out;
    float* out_hs  = (float*)d_out + (size_t)TSTEPS * BATCH * HC;

    float *A1p, *A2p, *h1sp;
    cudaGetSymbolAddress((void**)&A1p,  g_A1);
    cudaGetSymbolAddress((void**)&A2p,  g_A2);
    cudaGetSymbolAddress((void**)&h1sp, g_h1s);

    const int Mrows = TSTEPS * BATCH;   // 32768

    for (int l = 0; l < NLAYER; l++) {
        const float* in  = (l == 0) ? x : h1sp;
        const float* W1L = W1 + (size_t)l * W1ROWS * WLD;
        const float* W2L = W2 + (size_t)l * HC * WLD;

        input_gemm_kernel<<<dim3(W1ROWS / 64, Mrows / 64), 256>>>(
            in, W1L, b1 + (size_t)l * W1ROWS, A1p, W1ROWS);
        input_gemm_kernel<<<dim3(HC / 64, Mrows / 64), 256>>>(
            in, W2L, b2 + (size_t)l * HC, A2p, HC);

        layer_init_kernel<<<(BATCH * HC) / 256, 256>>>(hid + (size_t)l * HC);

        float* seq = (l == 0) ? h1sp : out_seq;
        float* fin = out_hs + (size_t)l * BATCH * HC;
        gru_persist<<<NCTA, 256>>>(W1L, W2L, A1p, A2p, seq, fin);
    }
}

// round 9
// speedup vs baseline: 1.0751x; 1.0751x over previous
#include <cuda_runtime.h>
#include <math.h>

// ---------------------------------------------------------------------------
// GRU T=512 B=64 IC=HC=512 L=2.
//   A1 = in @ W1x^T + b1  (parallel GEMM, 2*HC cols)
//   A2 = in @ W2x^T + b2  (parallel GEMM, HC cols)
//   per step: pre1 = A1[t] + h @ W1h^T ; r,z = sigmoid
//             pre2 = A2[t] + (r*h) @ W2h^T ; g = tanh ; h = z*h + (1-z)*g
// Recurrence: ONE persistent kernel per layer (128 CTAs, grid barrier).
// R8 changes: depth-4 L2 prefetch pipeline in both recurrent phases;
//             128x128x16 GEMM with 8x8 register tile + float4 LDS.
// ---------------------------------------------------------------------------

#define TSTEPS 512
#define BATCH  64
#define HC     512
#define NLAYER 2
#define W1ROWS 1024
#define WLD    1024
#define NCTA   128

__device__ float g_A1 [TSTEPS * BATCH * W1ROWS];
__device__ float g_A2 [TSTEPS * BATCH * HC];
__device__ float g_h1s[TSTEPS * BATCH * HC];
__device__ float g_hT [HC * BATCH];               // packed [(k>>2)*64+b]*4+(k&3)
__device__ float g_rhT[HC * BATCH];
__device__ float g_zT [HC * BATCH];               // [j*64 + b]
__device__ unsigned          g_arrive;
__device__ volatile unsigned g_gen;

// ---------------------------------------------------------------------------
// Grid barrier (monotonic counter + generation flag; 128 co-resident CTAs).
// ---------------------------------------------------------------------------
__device__ __forceinline__ void grid_barrier(unsigned n) {
    __syncthreads();
    if (threadIdx.x == 0) {
        __threadfence();
        unsigned a = atomicAdd(&g_arrive, 1u);
        if (a == n * NCTA + (NCTA - 1)) {
            atomicExch((unsigned*)&g_gen, n + 1u);
        } else {
            while (g_gen < n + 1u) { }
        }
        __threadfence();
    }
    __syncthreads();
}

// ---------------------------------------------------------------------------
// Input GEMM: C[n,j] = bias[j] + sum_{k<512} X[n,k]*W[j,k]
// BM=BN=128, BK=16, 256 threads, 8x8 register tile (split 4+4), float4 LDS,
// register prefetch of the next k-tile.
// ---------------------------------------------------------------------------
__global__ __launch_bounds__(256, 2) void input_gemm_kernel(
    const float* __restrict__ X, const float* __restrict__ W,
    const float* __restrict__ bias, float* __restrict__ C, int N)
{
    __shared__ float As[16][132];   // [k][m]
    __shared__ float Bs[16][132];   // [k][n]
    const int n0 = blockIdx.y * 128;     // M block (rows of X)
    const int j0 = blockIdx.x * 128;     // N block (rows of W)
    const int tid = threadIdx.x;
    const int tx = tid & 15, ty = tid >> 4;
    const int xr = tid >> 2, xc = tid & 3;

    const float* Xp0 = X + (size_t)(n0 + xr)      * 512 + xc * 4;
    const float* Xp1 = X + (size_t)(n0 + xr + 64) * 512 + xc * 4;
    const float* Wp0 = W + (size_t)(j0 + xr)      * WLD + xc * 4;
    const float* Wp1 = W + (size_t)(j0 + xr + 64) * WLD + xc * 4;

    float acc[8][8];
    #pragma unroll
    for (int u = 0; u < 8; u++)
        #pragma unroll
        for (int v = 0; v < 8; v++) acc[u][v] = 0.f;

    float4 xa = *(const float4*)Xp0;
    float4 xb = *(const float4*)Xp1;
    float4 wa = *(const float4*)Wp0;
    float4 wb = *(const float4*)Wp1;

    for (int k0 = 0; k0 < 512; k0 += 16) {
        As[xc*4+0][xr]      = xa.x; As[xc*4+1][xr]      = xa.y;
        As[xc*4+2][xr]      = xa.z; As[xc*4+3][xr]      = xa.w;
        As[xc*4+0][xr + 64] = xb.x; As[xc*4+1][xr + 64] = xb.y;
        As[xc*4+2][xr + 64] = xb.z; As[xc*4+3][xr + 64] = xb.w;
        Bs[xc*4+0][xr]      = wa.x; Bs[xc*4+1][xr]      = wa.y;
        Bs[xc*4+2][xr]      = wa.z; Bs[xc*4+3][xr]      = wa.w;
        Bs[xc*4+0][xr + 64] = wb.x; Bs[xc*4+1][xr + 64] = wb.y;
        Bs[xc*4+2][xr + 64] = wb.z; Bs[xc*4+3][xr + 64] = wb.w;
        __syncthreads();
        if (k0 + 16 < 512) {                 // register prefetch next tile
            xa = *(const float4*)(Xp0 + k0 + 16);
            xb = *(const float4*)(Xp1 + k0 + 16);
            wa = *(const float4*)(Wp0 + k0 + 16);
            wb = *(const float4*)(Wp1 + k0 + 16);
        }
        #pragma unroll
        for (int kk = 0; kk < 16; kk++) {
            const float4 a0 = *(const float4*)&As[kk][ty * 4];
            const float4 a1 = *(const float4*)&As[kk][ty * 4 + 64];
            const float4 b0 = *(const float4*)&Bs[kk][tx * 4];
            const float4 b1 = *(const float4*)&Bs[kk][tx * 4 + 64];
            const float am[8] = {a0.x,a0.y,a0.z,a0.w, a1.x,a1.y,a1.z,a1.w};
            const float bn[8] = {b0.x,b0.y,b0.z,b0.w, b1.x,b1.y,b1.z,b1.w};
            #pragma unroll
            for (int u = 0; u < 8; u++)
                #pragma unroll
                for (int v = 0; v < 8; v++)
                    acc[u][v] = fmaf(am[u], bn[v], acc[u][v]);
        }
        __syncthreads();
    }

    const float4 bb0 = *(const float4*)(bias + j0 + tx * 4);
    const float4 bb1 = *(const float4*)(bias + j0 + tx * 4 + 64);
    const float bv[8] = {bb0.x,bb0.y,bb0.z,bb0.w, bb1.x,bb1.y,bb1.z,bb1.w};
    #pragma unroll
    for (int u = 0; u < 8; u++) {
        const int m = n0 + ((u < 4) ? (ty * 4 + u) : (64 + ty * 4 + u - 4));
        float4 o0, o1;
        o0.x = acc[u][0] + bv[0]; o0.y = acc[u][1] + bv[1];
        o0.z = acc[u][2] + bv[2]; o0.w = acc[u][3] + bv[3];
        o1.x = acc[u][4] + bv[4]; o1.y = acc[u][5] + bv[5];
        o1.z = acc[u][6] + bv[6]; o1.w = acc[u][7] + bv[7];
        *(float4*)(C + (size_t)m * N + j0 + tx * 4)      = o0;
        *(float4*)(C + (size_t)m * N + j0 + tx * 4 + 64) = o1;
    }
}

// Per-layer init: broadcast h0 into packed hT, reset barrier state.
__global__ __launch_bounds__(256) void layer_init_kernel(const float* __restrict__ hid)
{
    const int i = blockIdx.x * 256 + threadIdx.x;
    const int b = i & 63, k = i >> 6;
    g_hT[((k >> 2) * 64 + b) * 4 + (k & 3)] = hid[k];
    if (i == 0) { g_arrive = 0u; *(unsigned*)&g_gen = 0u; }
}

// ---------------------------------------------------------------------------
// Persistent recurrent kernel. CTA c owns:
//   phase A: gate columns jg = c*8..c*8+7 (c<64: r, c>=64: z)
//   phase B: g columns    j  = c*4..c*4+3
// Warp w: b-half = w>>2, k-quarter = w&3.  Weights SMEM-resident all layer.
// Depth-4 prefetch pipeline on the L2 h / rh streams.
// ---------------------------------------------------------------------------
__global__ __launch_bounds__(256, 1) void gru_persist(
    const float* __restrict__ W1L, const float* __restrict__ W2L,
    const float* __restrict__ A1,  const float* __restrict__ A2,
    float* __restrict__ seq, float* __restrict__ hfin)
{
    __shared__ float WA[8 * 512];
    __shared__ float WB[4 * 512];
    __shared__ float red[8 * 32 * 8];

    const int c = blockIdx.x, tid = threadIdx.x;
    const int w = tid >> 5, lane = tid & 31;
    const int bh = w >> 2, kq = w & 3;
    const int b  = bh * 32 + lane;
    const int k40 = kq * 32;

    for (int i = tid; i < 8 * 512; i += 256)
        WA[i] = W1L[(size_t)(c * 8 + (i >> 9)) * WLD + 512 + (i & 511)];
    for (int i = tid; i < 4 * 512; i += 256)
        WB[i] = W2L[(size_t)(c * 4 + (i >> 9)) * WLD + 512 + (i & 511)];
    __syncthreads();

    const float4* hT4  = (const float4*)g_hT;
    const float4* rhT4 = (const float4*)g_rhT;
    const float4* WA4  = (const float4*)WA;
    const float4* WB4  = (const float4*)WB;

    const int b2  = tid >> 2;
    const int j0A = (tid & 3) * 2;
    const int jlB = tid & 3;
    const int jgA0 = c * 8 + j0A;
    const int jB   = c * 4 + jlB;

    for (int t = 0; t < TSTEPS; t++) {
        // =================== phase A: pre1 -> r,z ===================
        const float a10 = A1[((size_t)t * 64 + b2) * 1024 + jgA0];
        const float a11 = A1[((size_t)t * 64 + b2) * 1024 + jgA0 + 1];
        float hb0 = 0.f, hb1 = 0.f;
        if (c < 64) {
            hb0 = __ldcg(&g_hT[((jgA0 >> 2) * 64 + b2) * 4 + (jgA0 & 3)]);
            hb1 = __ldcg(&g_hT[(((jgA0 + 1) >> 2) * 64 + b2) * 4 + ((jgA0 + 1) & 3)]);
        }
        {
            float acc[8];
            #pragma unroll
            for (int jl = 0; jl < 8; jl++) acc[jl] = 0.f;
            const float4* hp = hT4 + (size_t)k40 * 64 + b;
            float4 buf[4];
            #pragma unroll
            for (int d = 0; d < 4; d++) buf[d] = __ldcg(hp + (size_t)d * 64);
            for (int ib = 0; ib < 8; ib++) {
                #pragma unroll
                for (int u = 0; u < 4; u++) {
                    const int i = ib * 4 + u;
                    const float4 hv = buf[u];
                    if (i + 4 < 32) buf[u] = __ldcg(hp + (size_t)(i + 4) * 64);
                    const int k4 = k40 + i;
                    #pragma unroll
                    for (int jl = 0; jl < 8; jl++) {
                        const float4 wv = WA4[jl * 128 + k4];
                        acc[jl] = fmaf(hv.x, wv.x, fmaf(hv.y, wv.y,
                                  fmaf(hv.z, wv.z, fmaf(hv.w, wv.w, acc[jl]))));
                    }
                }
            }
            float* rp = &red[(w * 32 + lane) * 8];
            #pragma unroll
            for (int jl = 0; jl < 8; jl++) rp[jl] = acc[jl];
        }
        __syncthreads();
        {
            const int bhh = b2 >> 5, bl = b2 & 31;
            #pragma unroll
            for (int u = 0; u < 2; u++) {
                float s = 0.f;
                #pragma unroll
                for (int q = 0; q < 4; q++)
                    s += red[((bhh * 4 + q) * 32 + bl) * 8 + j0A + u];
                const float pre = s + (u ? a11 : a10);
                const float sg = 1.f / (1.f + __expf(-pre));
                const int jg = jgA0 + u;
                if (c < 64) {
                    g_rhT[((jg >> 2) * 64 + b2) * 4 + (jg & 3)] = sg * (u ? hb1 : hb0);
                } else {
                    g_zT[(jg - 512) * 64 + b2] = sg;
                }
            }
        }
        grid_barrier(2u * t);

        // =================== phase B: pre2 -> g -> h ===================
        const float a2v  = A2[((size_t)t * 64 + b2) * 512 + jB];
        const float zv   = __ldcg(&g_zT[jB * 64 + b2]);
        const float hold = __ldcg(&g_hT[((jB >> 2) * 64 + b2) * 4 + (jB & 3)]);
        {
            float acc[4];
            #pragma unroll
            for (int jl = 0; jl < 4; jl++) acc[jl] = 0.f;
            const float4* rp4 = rhT4 + (size_t)k40 * 64 + b;
            float4 buf[4];
            #pragma unroll
            for (int d = 0; d < 4; d++) buf[d] = __ldcg(rp4 + (size_t)d * 64);
            for (int ib = 0; ib < 8; ib++) {
                #pragma unroll
                for (int u = 0; u < 4; u++) {
                    const int i = ib * 4 + u;
                    const float4 rv = buf[u];
                    if (i + 4 < 32) buf[u] = __ldcg(rp4 + (size_t)(i + 4) * 64);
                    const int k4 = k40 + i;
                    #pragma unroll
                    for (int jl = 0; jl < 4; jl++) {
                        const float4 wv = WB4[jl * 128 + k4];
                        acc[jl] = fmaf(rv.x, wv.x, fmaf(rv.y, wv.y,
                                  fmaf(rv.z, wv.z, fmaf(rv.w, wv.w, acc[jl]))));
                    }
                }
            }
            float* rp = &red[(w * 32 + lane) * 4];
            #pragma unroll
            for (int jl = 0; jl < 4; jl++) rp[jl] = acc[jl];
        }
        __syncthreads();
        {
            const int bhh = b2 >> 5, bl = b2 & 31;
            float s = 0.f;
            #pragma unroll
            for (int q = 0; q < 4; q++)
                s += red[((bhh * 4 + q) * 32 + bl) * 4 + jlB];
            const float g  = tanhf(s + a2v);
            const float hn = zv * hold + (1.f - zv) * g;
            g_hT[((jB >> 2) * 64 + b2) * 4 + (jB & 3)] = hn;
            seq[((size_t)t * 64 + b2) * 512 + jB] = hn;
            if (t == TSTEPS - 1) hfin[b2 * 512 + jB] = hn;
        }
        grid_barrier(2u * t + 1u);
    }
}

// ---------------------------------------------------------------------------
// Inputs: x[512,64,512], hiddens[2,1,512], W1[2,1024,1024], b1[2,1024],
//         W2[2,512,1024], b2[2,512]
// Output: out_seq[512,64,512] ++ hs[2,64,512]
// ---------------------------------------------------------------------------
extern "C" void kernel_launch(void* const* d_in, const int* in_sizes, int n_in,
                              void* d_out, int out_size)
{
    const float* x   = (const float*)d_in[0];
    const float* hid = (const float*)d_in[1];
    const float* W1  = (const float*)d_in[2];
    const float* b1  = (const float*)d_in[3];
    const float* W2  = (const float*)d_in[4];
    const float* b2  = (const float*)d_in[5];

    float* out_seq = (float*)d_out;
    float* out_hs  = (float*)d_out + (size_t)TSTEPS * BATCH * HC;

    float *A1p, *A2p, *h1sp;
    cudaGetSymbolAddress((void**)&A1p,  g_A1);
    cudaGetSymbolAddress((void**)&A2p,  g_A2);
    cudaGetSymbolAddress((void**)&h1sp, g_h1s);

    const int Mrows = TSTEPS * BATCH;   // 32768

    for (int l = 0; l < NLAYER; l++) {
        const float* in  = (l == 0) ? x : h1sp;
        const float* W1L = W1 + (size_t)l * W1ROWS * WLD;
        const float* W2L = W2 + (size_t)l * HC * WLD;

        input_gemm_kernel<<<dim3(W1ROWS / 128, Mrows / 128), 256>>>(
            in, W1L, b1 + (size_t)l * W1ROWS, A1p, W1ROWS);
        input_gemm_kernel<<<dim3(HC / 128, Mrows / 128), 256>>>(
            in, W2L, b2 + (size_t)l * HC, A2p, HC);

        layer_init_kernel<<<(BATCH * HC) / 256, 256>>>(hid + (size_t)l * HC);

        float* seq = (l == 0) ? h1sp : out_seq;
        float* fin = out_hs + (size_t)l * BATCH * HC;
        gru_persist<<<NCTA, 256>>>(W1L, W2L, A1p, A2p, seq, fin);
    }
}

// round 10
// speedup vs baseline: 1.1949x; 1.1114x over previous
#include <cuda_runtime.h>
#include <math.h>

// ---------------------------------------------------------------------------
// GRU T=512 B=64 IC=HC=512 L=2.
//   A1 = in @ W1x^T + b1  (parallel GEMM)
//   A2 = in @ W2x^T + b2  (parallel GEMM)
//   per step: pre1 = A1[t] + h @ W1h^T ; r,z = sigmoid
//             pre2 = A2[t] + (r*h) @ W2h^T ; g = tanh ; h = z*h + (1-z)*g
// Recurrence: ONE persistent kernel per layer (128 CTAs, grid barrier).
// R9: fma.rn.f32x2 (FFMA2) in both GEMM and recurrence inner loops (2x fp32
//     pipe rate, bit-identical math); SMEM weights repacked as j-pairs;
//     depth-8 LDG pipeline on the h / r*h L2 streams.
// ---------------------------------------------------------------------------

#define TSTEPS 512
#define BATCH  64
#define HC     512
#define NLAYER 2
#define W1ROWS 1024
#define WLD    1024
#define NCTA   128

// Packed fp32x2 ops (Blackwell FFMA2 path)
#define FFMA2(d, a, b) \
    asm("fma.rn.f32x2 %0, %1, %2, %0;" : "+l"(d) : "l"(a), "l"(b))
#define PACK2(d, lo, hi) \
    asm("mov.b64 %0, {%1, %2};" : "=l"(d) : "r"(__float_as_uint(lo)), "r"(__float_as_uint(hi)))
#define UNPACK2(lo, hi, s) do { unsigned _ulo, _uhi; \
    asm("mov.b64 {%0, %1}, %2;" : "=r"(_ulo), "=r"(_uhi) : "l"(s)); \
    lo = __uint_as_float(_ulo); hi = __uint_as_float(_uhi); } while (0)

__device__ float g_A1 [TSTEPS * BATCH * W1ROWS];
__device__ float g_A2 [TSTEPS * BATCH * HC];
__device__ float g_h1s[TSTEPS * BATCH * HC];
__device__ float g_hT [HC * BATCH];               // packed [(k>>2)*64+b]*4+(k&3)
__device__ float g_rhT[HC * BATCH];
__device__ float g_zT [HC * BATCH];               // [j*64 + b]
__device__ unsigned          g_arrive;
__device__ volatile unsigned g_gen;

// ---------------------------------------------------------------------------
// Grid barrier (monotonic counter + generation flag; 128 co-resident CTAs).
// ---------------------------------------------------------------------------
__device__ __forceinline__ void grid_barrier(unsigned n) {
    __syncthreads();
    if (threadIdx.x == 0) {
        __threadfence();
        unsigned a = atomicAdd(&g_arrive, 1u);
        if (a == n * NCTA + (NCTA - 1)) {
            atomicExch((unsigned*)&g_gen, n + 1u);
        } else {
            while (g_gen < n + 1u) { }
        }
        __threadfence();
    }
    __syncthreads();
}

// ---------------------------------------------------------------------------
// Input GEMM: C[n,j] = bias[j] + sum_{k<512} X[n,k]*W[j,k]
// BM=BN=128, BK=16, 256 threads, 8x8 register tile via f32x2 pairs.
// ---------------------------------------------------------------------------
__global__ __launch_bounds__(256, 2) void input_gemm_kernel(
    const float* __restrict__ X, const float* __restrict__ W,
    const float* __restrict__ bias, float* __restrict__ C, int N)
{
    __shared__ float As[16][132];
    __shared__ float Bs[16][132];
    const int n0 = blockIdx.y * 128;
    const int j0 = blockIdx.x * 128;
    const int tid = threadIdx.x;
    const int tx = tid & 15, ty = tid >> 4;
    const int xr = tid >> 2, xc = tid & 3;

    const float* Xp0 = X + (size_t)(n0 + xr)      * 512 + xc * 4;
    const float* Xp1 = X + (size_t)(n0 + xr + 64) * 512 + xc * 4;
    const float* Wp0 = W + (size_t)(j0 + xr)      * WLD + xc * 4;
    const float* Wp1 = W + (size_t)(j0 + xr + 64) * WLD + xc * 4;

    unsigned long long acc2[8][4];
    #pragma unroll
    for (int u = 0; u < 8; u++)
        #pragma unroll
        for (int p = 0; p < 4; p++) acc2[u][p] = 0ull;

    float4 xa = *(const float4*)Xp0;
    float4 xb = *(const float4*)Xp1;
    float4 wa = *(const float4*)Wp0;
    float4 wb = *(const float4*)Wp1;

    for (int k0 = 0; k0 < 512; k0 += 16) {
        As[xc*4+0][xr]      = xa.x; As[xc*4+1][xr]      = xa.y;
        As[xc*4+2][xr]      = xa.z; As[xc*4+3][xr]      = xa.w;
        As[xc*4+0][xr + 64] = xb.x; As[xc*4+1][xr + 64] = xb.y;
        As[xc*4+2][xr + 64] = xb.z; As[xc*4+3][xr + 64] = xb.w;
        Bs[xc*4+0][xr]      = wa.x; Bs[xc*4+1][xr]      = wa.y;
        Bs[xc*4+2][xr]      = wa.z; Bs[xc*4+3][xr]      = wa.w;
        Bs[xc*4+0][xr + 64] = wb.x; Bs[xc*4+1][xr + 64] = wb.y;
        Bs[xc*4+2][xr + 64] = wb.z; Bs[xc*4+3][xr + 64] = wb.w;
        __syncthreads();
        if (k0 + 16 < 512) {
            xa = *(const float4*)(Xp0 + k0 + 16);
            xb = *(const float4*)(Xp1 + k0 + 16);
            wa = *(const float4*)(Wp0 + k0 + 16);
            wb = *(const float4*)(Wp1 + k0 + 16);
        }
        #pragma unroll
        for (int kk = 0; kk < 16; kk++) {
            const float4 a0 = *(const float4*)&As[kk][ty * 4];
            const float4 a1 = *(const float4*)&As[kk][ty * 4 + 64];
            const ulonglong2 bp0 = *(const ulonglong2*)&Bs[kk][tx * 4];
            const ulonglong2 bp1 = *(const ulonglong2*)&Bs[kk][tx * 4 + 64];
            const unsigned long long bp[4] = {bp0.x, bp0.y, bp1.x, bp1.y};
            const float am[8] = {a0.x,a0.y,a0.z,a0.w, a1.x,a1.y,a1.z,a1.w};
            #pragma unroll
            for (int u = 0; u < 8; u++) {
                unsigned long long ad; PACK2(ad, am[u], am[u]);
                #pragma unroll
                for (int p = 0; p < 4; p++) FFMA2(acc2[u][p], ad, bp[p]);
            }
        }
        __syncthreads();
    }

    const float4 bb0 = *(const float4*)(bias + j0 + tx * 4);
    const float4 bb1 = *(const float4*)(bias + j0 + tx * 4 + 64);
    const float bv[8] = {bb0.x,bb0.y,bb0.z,bb0.w, bb1.x,bb1.y,bb1.z,bb1.w};
    #pragma unroll
    for (int u = 0; u < 8; u++) {
        const int m = n0 + ((u < 4) ? (ty * 4 + u) : (64 + ty * 4 + u - 4));
        float cf[8];
        #pragma unroll
        for (int p = 0; p < 4; p++) UNPACK2(cf[2*p], cf[2*p+1], acc2[u][p]);
        float4 o0, o1;
        o0.x = cf[0] + bv[0]; o0.y = cf[1] + bv[1];
        o0.z = cf[2] + bv[2]; o0.w = cf[3] + bv[3];
        o1.x = cf[4] + bv[4]; o1.y = cf[5] + bv[5];
        o1.z = cf[6] + bv[6]; o1.w = cf[7] + bv[7];
        *(float4*)(C + (size_t)m * N + j0 + tx * 4)      = o0;
        *(float4*)(C + (size_t)m * N + j0 + tx * 4 + 64) = o1;
    }
}

// Per-layer init: broadcast h0 into packed hT, reset barrier state.
__global__ __launch_bounds__(256) void layer_init_kernel(const float* __restrict__ hid)
{
    const int i = blockIdx.x * 256 + threadIdx.x;
    const int b = i & 63, k = i >> 6;
    g_hT[((k >> 2) * 64 + b) * 4 + (k & 3)] = hid[k];
    if (i == 0) { g_arrive = 0u; *(unsigned*)&g_gen = 0u; }
}

// ---------------------------------------------------------------------------
// Persistent recurrent kernel. CTA c owns:
//   phase A: gate columns jg = c*8..c*8+7 (c<64: r, c>=64: z)
//   phase B: g columns    j  = c*4..c*4+3
// Warp w: b-half = w>>2, k-quarter = w&3. Weights SMEM-resident as f32x2
// j-pairs: WAp[k*4+p] = {W1h[2p][k], W1h[2p+1][k]}. Depth-8 LDG pipeline.
// ---------------------------------------------------------------------------
__global__ __launch_bounds__(256, 1) void gru_persist(
    const float* __restrict__ W1L, const float* __restrict__ W2L,
    const float* __restrict__ A1,  const float* __restrict__ A2,
    float* __restrict__ seq, float* __restrict__ hfin)
{
    __shared__ unsigned long long WAp[512 * 4];   // 16 KB
    __shared__ unsigned long long WBp[512 * 2];   //  8 KB
    __shared__ float red[8 * 32 * 8];             //  8 KB

    const int c = blockIdx.x, tid = threadIdx.x;
    const int w = tid >> 5, lane = tid & 31;
    const int bh = w >> 2, kq = w & 3;
    const int b  = bh * 32 + lane;
    const int k40 = kq * 32;

    for (int i = tid; i < 512 * 4; i += 256) {
        const int k = i >> 2, p = i & 3;
        const float w0 = W1L[(size_t)(c * 8 + 2 * p)     * WLD + 512 + k];
        const float w1 = W1L[(size_t)(c * 8 + 2 * p + 1) * WLD + 512 + k];
        unsigned long long u; PACK2(u, w0, w1);
        WAp[k * 4 + p] = u;
    }
    for (int i = tid; i < 512 * 2; i += 256) {
        const int k = i >> 1, p = i & 1;
        const float w0 = W2L[(size_t)(c * 4 + 2 * p)     * WLD + 512 + k];
        const float w1 = W2L[(size_t)(c * 4 + 2 * p + 1) * WLD + 512 + k];
        unsigned long long u; PACK2(u, w0, w1);
        WBp[k * 2 + p] = u;
    }
    __syncthreads();

    const float4* hT4  = (const float4*)g_hT;
    const float4* rhT4 = (const float4*)g_rhT;

    const int b2  = tid >> 2;
    const int j0A = (tid & 3) * 2;
    const int jlB = tid & 3;
    const int jgA0 = c * 8 + j0A;
    const int jB   = c * 4 + jlB;

    for (int t = 0; t < TSTEPS; t++) {
        // =================== phase A: pre1 -> r,z ===================
        const float a10 = A1[((size_t)t * 64 + b2) * 1024 + jgA0];
        const float a11 = A1[((size_t)t * 64 + b2) * 1024 + jgA0 + 1];
        float hb0 = 0.f, hb1 = 0.f;
        if (c < 64) {
            hb0 = __ldcg(&g_hT[((jgA0 >> 2) * 64 + b2) * 4 + (jgA0 & 3)]);
            hb1 = __ldcg(&g_hT[(((jgA0 + 1) >> 2) * 64 + b2) * 4 + ((jgA0 + 1) & 3)]);
        }
        {
            unsigned long long acc2[4] = {0ull, 0ull, 0ull, 0ull};
            const float4* hp = hT4 + (size_t)k40 * 64 + b;
            float4 buf[8];
            #pragma unroll
            for (int d = 0; d < 8; d++) buf[d] = __ldcg(hp + (size_t)d * 64);
            #pragma unroll
            for (int ib = 0; ib < 4; ib++) {
                #pragma unroll
                for (int u = 0; u < 8; u++) {
                    const int i = ib * 8 + u;
                    const float4 hv = buf[u];
                    if (i + 8 < 32) buf[u] = __ldcg(hp + (size_t)(i + 8) * 64);
                    const float hs[4] = {hv.x, hv.y, hv.z, hv.w};
                    #pragma unroll
                    for (int s = 0; s < 4; s++) {
                        const int ks = (k40 + i) * 4 + s;
                        unsigned long long hd; PACK2(hd, hs[s], hs[s]);
                        const ulonglong2 w01 = *(const ulonglong2*)&WAp[ks * 4];
                        const ulonglong2 w23 = *(const ulonglong2*)&WAp[ks * 4 + 2];
                        FFMA2(acc2[0], hd, w01.x);
                        FFMA2(acc2[1], hd, w01.y);
                        FFMA2(acc2[2], hd, w23.x);
                        FFMA2(acc2[3], hd, w23.y);
                    }
                }
            }
            float* rp = &red[(w * 32 + lane) * 8];
            #pragma unroll
            for (int p = 0; p < 4; p++) {
                float lo, hi; UNPACK2(lo, hi, acc2[p]);
                rp[2 * p] = lo; rp[2 * p + 1] = hi;
            }
        }
        __syncthreads();
        {
            const int bhh = b2 >> 5, bl = b2 & 31;
            #pragma unroll
            for (int u = 0; u < 2; u++) {
                float s = 0.f;
                #pragma unroll
                for (int q = 0; q < 4; q++)
                    s += red[((bhh * 4 + q) * 32 + bl) * 8 + j0A + u];
                const float pre = s + (u ? a11 : a10);
                const float sg = 1.f / (1.f + __expf(-pre));
                const int jg = jgA0 + u;
                if (c < 64) {
                    g_rhT[((jg >> 2) * 64 + b2) * 4 + (jg & 3)] = sg * (u ? hb1 : hb0);
                } else {
                    g_zT[(jg - 512) * 64 + b2] = sg;
                }
            }
        }
        grid_barrier(2u * t);

        // =================== phase B: pre2 -> g -> h ===================
        const float a2v  = A2[((size_t)t * 64 + b2) * 512 + jB];
        const float zv   = __ldcg(&g_zT[jB * 64 + b2]);
        const float hold = __ldcg(&g_hT[((jB >> 2) * 64 + b2) * 4 + (jB & 3)]);
        {
            unsigned long long acc2[2] = {0ull, 0ull};
            const float4* rp4 = rhT4 + (size_t)k40 * 64 + b;
            float4 buf[8];
            #pragma unroll
            for (int d = 0; d < 8; d++) buf[d] = __ldcg(rp4 + (size_t)d * 64);
            #pragma unroll
            for (int ib = 0; ib < 4; ib++) {
                #pragma unroll
                for (int u = 0; u < 8; u++) {
                    const int i = ib * 8 + u;
                    const float4 rv = buf[u];
                    if (i + 8 < 32) buf[u] = __ldcg(rp4 + (size_t)(i + 8) * 64);
                    const float rs[4] = {rv.x, rv.y, rv.z, rv.w};
                    #pragma unroll
                    for (int s = 0; s < 4; s++) {
                        const int ks = (k40 + i) * 4 + s;
                        unsigned long long rd; PACK2(rd, rs[s], rs[s]);
                        const ulonglong2 w01 = *(const ulonglong2*)&WBp[ks * 2];
                        FFMA2(acc2[0], rd, w01.x);
                        FFMA2(acc2[1], rd, w01.y);
                    }
                }
            }
            float* rp = &red[(w * 32 + lane) * 4];
            #pragma unroll
            for (int p = 0; p < 2; p++) {
                float lo, hi; UNPACK2(lo, hi, acc2[p]);
                rp[2 * p] = lo; rp[2 * p + 1] = hi;
            }
        }
        __syncthreads();
        {
            const int bhh = b2 >> 5, bl = b2 & 31;
            float s = 0.f;
            #pragma unroll
            for (int q = 0; q < 4; q++)
                s += red[((bhh * 4 + q) * 32 + bl) * 4 + jlB];
            const float g  = tanhf(s + a2v);
            const float hn = zv * hold + (1.f - zv) * g;
            g_hT[((jB >> 2) * 64 + b2) * 4 + (jB & 3)] = hn;
            seq[((size_t)t * 64 + b2) * 512 + jB] = hn;
            if (t == TSTEPS - 1) hfin[b2 * 512 + jB] = hn;
        }
        grid_barrier(2u * t + 1u);
    }
}

// ---------------------------------------------------------------------------
// Inputs: x[512,64,512], hiddens[2,1,512], W1[2,1024,1024], b1[2,1024],
//         W2[2,512,1024], b2[2,512]
// Output: out_seq[512,64,512] ++ hs[2,64,512]
// ---------------------------------------------------------------------------
extern "C" void kernel_launch(void* const* d_in, const int* in_sizes, int n_in,
                              void* d_out, int out_size)
{
    const float* x   = (const float*)d_in[0];
    const float* hid = (const float*)d_in[1];
    const float* W1  = (const float*)d_in[2];
    const float* b1  = (const float*)d_in[3];
    const float* W2  = (const float*)d_in[4];
    const float* b2  = (const float*)d_in[5];

    float* out_seq = (float*)d_out;
    float* out_hs  = (float*)d_out + (size_t)TSTEPS * BATCH * HC;

    float *A1p, *A2p, *h1sp;
    cudaGetSymbolAddress((void**)&A1p,  g_A1);
    cudaGetSymbolAddress((void**)&A2p,  g_A2);
    cudaGetSymbolAddress((void**)&h1sp, g_h1s);

    const int Mrows = TSTEPS * BATCH;   // 32768

    for (int l = 0; l < NLAYER; l++) {
        const float* in  = (l == 0) ? x : h1sp;
        const float* W1L = W1 + (size_t)l * W1ROWS * WLD;
        const float* W2L = W2 + (size_t)l * HC * WLD;

        input_gemm_kernel<<<dim3(W1ROWS / 128, Mrows / 128), 256>>>(
            in, W1L, b1 + (size_t)l * W1ROWS, A1p, W1ROWS);
        input_gemm_kernel<<<dim3(HC / 128, Mrows / 128), 256>>>(
            in, W2L, b2 + (size_t)l * HC, A2p, HC);

        layer_init_kernel<<<(BATCH * HC) / 256, 256>>>(hid + (size_t)l * HC);

        float* seq = (l == 0) ? h1sp : out_seq;
        float* fin = out_hs + (size_t)l * BATCH * HC;
        gru_persist<<<NCTA, 256>>>(W1L, W2L, A1p, A2p, seq, fin);
    }
}

// round 13
// speedup vs baseline: 1.3424x; 1.1235x over previous
#include <cuda_runtime.h>
#include <math.h>

// ---------------------------------------------------------------------------
// GRU T=512 B=64 IC=HC=512 L=2 — fully fused wavefront persistent kernel.
//
// 128 CTAs: c<64 -> layer 1, c>=64 -> layer 2 (offset one step: wavefront i
// runs L1 step i and L2 step i-1). Each CTA owns 16 gate cols (8 r + 8 z) and
// 8 g cols; it keeps the FULL 1024-wide (x||h) weight rows in SMEM, so the
// former input GEMMs are absorbed into the recurrent dot products.
// Per wavefront: phase A (pre1 -> r,z), grid barrier, phase B (pre2 -> g -> h),
// grid barrier. h per (b,j) lives in registers of its combine thread.
// Graph = 2 nodes: prep (x transpose + h0 broadcast + barrier reset), persist.
// ---------------------------------------------------------------------------

#define TSTEPS 512
#define BATCH  64
#define HC     512
#define NCTA   128

#define FFMA2(d, a, b) \
    asm("fma.rn.f32x2 %0, %1, %2, %0;" : "+l"(d) : "l"(a), "l"(b))
#define PACK2(d, lo, hi) \
    asm("mov.b64 %0, {%1, %2};" : "=l"(d) : "r"(__float_as_uint(lo)), "r"(__float_as_uint(hi)))
#define UNPACK2(lo, hi, s) do { unsigned _ulo, _uhi; \
    asm("mov.b64 {%0, %1}, %2;" : "=r"(_ulo), "=r"(_uhi) : "l"(s)); \
    lo = __uint_as_float(_ulo); hi = __uint_as_float(_uhi); } while (0)

// Packed streaming layouts: [k4][b][s] (float4 per (k4,b))
__device__ float g_xT [TSTEPS * BATCH * HC];   // transposed x, per t: [128][64][4]
__device__ float g_h1T[TSTEPS * BATCH * HC];   // layer-1 outputs, same packing
__device__ float g_hT [2 * BATCH * HC];        // per-layer current h
__device__ float g_rhT[2 * BATCH * HC];        // per-layer r*h
__device__ unsigned          g_arrive;
__device__ volatile unsigned g_gen;

__device__ __forceinline__ void grid_barrier(unsigned n) {
    __syncthreads();
    if (threadIdx.x == 0) {
        __threadfence();
        unsigned a = atomicAdd(&g_arrive, 1u);
        if (a == n * NCTA + (NCTA - 1)) {
            atomicExch((unsigned*)&g_gen, n + 1u);
        } else {
            while (g_gen < n + 1u) { }
        }
        __threadfence();
    }
    __syncthreads();
}

// K-quarter dot: 64 float4 k-groups streamed from global (stride 64 float4),
// NJP f32x2 accumulators against SMEM-packed weight pairs Wq[(i*4+s)*NJP+jp].
template<bool USE_L1, int NJP>
__device__ __forceinline__ void dot_q(const float4* __restrict__ sp,
                                      const unsigned long long* __restrict__ Wq,
                                      unsigned long long* acc)
{
    float4 buf[4];
    #pragma unroll
    for (int d = 0; d < 4; d++)
        buf[d] = USE_L1 ? __ldg(sp + (size_t)d * 64) : __ldcg(sp + (size_t)d * 64);
    #pragma unroll 2
    for (int ib = 0; ib < 16; ib++) {
        #pragma unroll
        for (int u = 0; u < 4; u++) {
            const int i = ib * 4 + u;
            const float4 v = buf[u];
            if (i + 4 < 64)
                buf[u] = USE_L1 ? __ldg(sp + (size_t)(i + 4) * 64)
                                : __ldcg(sp + (size_t)(i + 4) * 64);
            const float vs[4] = {v.x, v.y, v.z, v.w};
            #pragma unroll
            for (int s = 0; s < 4; s++) {
                unsigned long long vd; PACK2(vd, vs[s], vs[s]);
                const unsigned long long* wp = Wq + (size_t)(i * 4 + s) * NJP;
                #pragma unroll
                for (int jp = 0; jp < NJP; jp += 2) {
                    const ulonglong2 wv = *(const ulonglong2*)(wp + jp);
                    FFMA2(acc[jp],     vd, wv.x);
                    FFMA2(acc[jp + 1], vd, wv.y);
                }
            }
        }
    }
}

// Prep: transpose x into packed layout, broadcast h0, reset barrier.
__global__ __launch_bounds__(256) void prep_kernel(const float* __restrict__ x,
                                                   const float* __restrict__ hid)
{
    const size_t o = (size_t)blockIdx.x * 256 + threadIdx.x;   // T*B*HC
    const int s  = (int)(o & 3);
    const int b  = (int)((o >> 2) & 63);
    const int k4 = (int)((o >> 8) & 127);
    const size_t t = o >> 15;
    g_xT[o] = x[(t * 64 + b) * 512 + k4 * 4 + s];
    if (o < 2 * 32768) {                       // h0 broadcast (b-independent)
        const int l = (int)(o >> 15);
        g_hT[o] = hid[l * 512 + k4 * 4 + s];
    }
    if (o == 0) { g_arrive = 0u; *(unsigned*)&g_gen = 0u; }
}

// ---------------------------------------------------------------------------
// Persistent fused GRU.
// SMEM: WAp [1024][8] f32x2 pairs (jp<4: r cols cl*8+2jp,+1; jp>=4: z cols)
//       WBp [1024][4] pairs (g cols), red [jp][256], zbuf [64][8].
// Warp w: kq=w&3 (k-quarter of 1024), bh=w>>2; lane = b within half.
// Combine thread tid: b2=tid>>2, q=tid&3 owns cols j0=cl*8+2q, j0+1; its h
// values stay in registers for the whole sequence.
// ---------------------------------------------------------------------------
__global__ __launch_bounds__(256, 1) void gru_fused(
    const float* __restrict__ W1, const float* __restrict__ W2,
    const float* __restrict__ bias1, const float* __restrict__ bias2,
    const float* __restrict__ hid,
    float* __restrict__ out_seq, float* __restrict__ out_hs)
{
    extern __shared__ unsigned long long smem[];
    unsigned long long* WAp = smem;            // 8192 ull = 64 KB
    unsigned long long* WBp = WAp + 8192;      // 4096 ull = 32 KB
    unsigned long long* red = WBp + 4096;      // 2048 ull = 16 KB
    float* zbuf = (float*)(red + 2048);        //  512 f   =  2 KB

    const int c = blockIdx.x, tid = threadIdx.x;
    const int layer = c >> 6, cl = c & 63;
    const int w = tid >> 5, lane = tid & 31;
    const int kq = w & 3, bh = w >> 2;
    const int b = bh * 32 + lane;

    const float* W1L = W1 + (size_t)layer * 1024 * 1024;
    const float* W2L = W2 + (size_t)layer * 512 * 1024;

    // Load + pack weights (coalesced over k)
    for (int i = tid; i < 8192; i += 256) {
        const int jp = i >> 10, k = i & 1023;
        const int jr = (jp < 4) ? (cl * 8 + 2 * jp) : (512 + cl * 8 + 2 * (jp - 4));
        unsigned long long u;
        PACK2(u, W1L[(size_t)jr * 1024 + k], W1L[(size_t)(jr + 1) * 1024 + k]);
        WAp[(size_t)k * 8 + jp] = u;
    }
    for (int i = tid; i < 4096; i += 256) {
        const int jp = i >> 10, k = i & 1023;
        const int jr = cl * 8 + 2 * jp;
        unsigned long long u;
        PACK2(u, W2L[(size_t)jr * 1024 + k], W2L[(size_t)(jr + 1) * 1024 + k]);
        WBp[(size_t)k * 4 + jp] = u;
    }

    // Combine-thread constants + register-resident h
    const int b2 = tid >> 2, q = tid & 3;
    const int j0 = cl * 8 + 2 * q;
    const float bR0 = bias1[(size_t)layer * 1024 + j0];
    const float bR1 = bias1[(size_t)layer * 1024 + j0 + 1];
    const float bZ0 = bias1[(size_t)layer * 1024 + 512 + j0];
    const float bZ1 = bias1[(size_t)layer * 1024 + 512 + j0 + 1];
    const float bG0 = bias2[(size_t)layer * 512 + j0];
    const float bG1 = bias2[(size_t)layer * 512 + j0 + 1];
    float h0r = hid[layer * 512 + j0];
    float h1r = hid[layer * 512 + j0 + 1];

    float* hTl  = g_hT  + (size_t)layer * 32768;
    float* rhTl = g_rhT + (size_t)layer * 32768;
    const float4* hT4  = (const float4*)hTl;
    const float4* rhT4 = (const float4*)rhTl;
    const int bh2 = b2 >> 5, bl = b2 & 31;

    __syncthreads();

    for (int wf = 0; wf <= TSTEPS; wf++) {
        const bool active = layer ? (wf >= 1) : (wf < TSTEPS);
        const int t = layer ? (wf - 1) : wf;
        const float4* xsrc = (const float4*)((layer ? g_h1T : g_xT) + (size_t)t * 32768);

        if (active) {
            // ---------- phase A: pre1 -> r, z ----------
            unsigned long long acc[8] = {0,0,0,0,0,0,0,0};
            if (kq < 2)
                dot_q<true , 8>(xsrc + (size_t)(kq * 64) * 64 + b,
                                WAp + (size_t)(kq * 256) * 8, acc);
            else
                dot_q<false, 8>(hT4 + (size_t)((kq - 2) * 64) * 64 + b,
                                WAp + (size_t)(kq * 256) * 8, acc);
            #pragma unroll
            for (int jp = 0; jp < 8; jp++) red[jp * 256 + tid] = acc[jp];
            __syncthreads();
            {
                float sr0 = 0.f, sr1 = 0.f, sz0 = 0.f, sz1 = 0.f;
                #pragma unroll
                for (int kk = 0; kk < 4; kk++) {
                    const int idx = (bh2 * 4 + kk) * 32 + bl;
                    float lo, hi;
                    UNPACK2(lo, hi, red[q * 256 + idx]);        sr0 += lo; sr1 += hi;
                    UNPACK2(lo, hi, red[(q + 4) * 256 + idx]);  sz0 += lo; sz1 += hi;
                }
                const float r0 = 1.f / (1.f + __expf(-(sr0 + bR0)));
                const float r1 = 1.f / (1.f + __expf(-(sr1 + bR1)));
                const float z0 = 1.f / (1.f + __expf(-(sz0 + bZ0)));
                const float z1 = 1.f / (1.f + __expf(-(sz1 + bZ1)));
                zbuf[b2 * 8 + 2 * q]     = z0;
                zbuf[b2 * 8 + 2 * q + 1] = z1;
                float2 rh; rh.x = r0 * h0r; rh.y = r1 * h1r;
                *(float2*)&rhTl[((j0 >> 2) * 64 + b2) * 4 + (j0 & 3)] = rh;
            }
        }
        grid_barrier(2u * (unsigned)wf);

        if (active) {
            // ---------- phase B: pre2 -> g -> h ----------
            unsigned long long acc[4] = {0,0,0,0};
            if (kq < 2)
                dot_q<true , 4>(xsrc + (size_t)(kq * 64) * 64 + b,
                                WBp + (size_t)(kq * 256) * 4, acc);
            else
                dot_q<false, 4>(rhT4 + (size_t)((kq - 2) * 64) * 64 + b,
                                WBp + (size_t)(kq * 256) * 4, acc);
            #pragma unroll
            for (int jp = 0; jp < 4; jp++) red[jp * 256 + tid] = acc[jp];
            __syncthreads();
            {
                float s0 = 0.f, s1 = 0.f;
                #pragma unroll
                for (int kk = 0; kk < 4; kk++) {
                    const int idx = (bh2 * 4 + kk) * 32 + bl;
                    float lo, hi;
                    UNPACK2(lo, hi, red[q * 256 + idx]); s0 += lo; s1 += hi;
                }
                const float g0 = tanhf(s0 + bG0);
                const float g1 = tanhf(s1 + bG1);
                const float z0 = zbuf[b2 * 8 + 2 * q];
                const float z1 = zbuf[b2 * 8 + 2 * q + 1];
                const float hn0 = z0 * h0r + (1.f - z0) * g0;
                const float hn1 = z1 * h1r + (1.f - z1) * g1;
                h0r = hn0; h1r = hn1;
                float2 hv; hv.x = hn0; hv.y = hn1;
                *(float2*)&hTl[((j0 >> 2) * 64 + b2) * 4 + (j0 & 3)] = hv;
                if (layer == 0)
                    *(float2*)&g_h1T[((size_t)t * 128 + (j0 >> 2)) * 256 + b2 * 4 + (j0 & 3)] = hv;
                else
                    *(float2*)&out_seq[((size_t)t * 64 + b2) * 512 + j0] = hv;
                if (t == TSTEPS - 1)
                    *(float2*)&out_hs[(size_t)layer * 32768 + b2 * 512 + j0] = hv;
            }
        }
        grid_barrier(2u * (unsigned)wf + 1u);
    }
}

// ---------------------------------------------------------------------------
// Inputs: x[512,64,512], hiddens[2,1,512], W1[2,1024,1024], b1[2,1024],
//         W2[2,512,1024], b2[2,512]
// Output: out_seq[512,64,512] ++ hs[2,64,512]
// ---------------------------------------------------------------------------
extern "C" void kernel_launch(void* const* d_in, const int* in_sizes, int n_in,
                              void* d_out, int out_size)
{
    const float* x   = (const float*)d_in[0];
    const float* hid = (const float*)d_in[1];
    const float* W1  = (const float*)d_in[2];
    const float* b1  = (const float*)d_in[3];
    const float* W2  = (const float*)d_in[4];
    const float* b2  = (const float*)d_in[5];

    float* out_seq = (float*)d_out;
    float* out_hs  = (float*)d_out + (size_t)TSTEPS * BATCH * HC;

    const int SMEM_BYTES = 116736;   // 64K + 32K + 16K + 2K
    cudaFuncSetAttribute(gru_fused, cudaFuncAttributeMaxDynamicSharedMemorySize,
                         SMEM_BYTES);

    prep_kernel<<<(TSTEPS * BATCH * HC) / 256, 256>>>(x, hid);
    gru_fused<<<NCTA, 256, SMEM_BYTES>>>(W1, W2, b1, b2, hid, out_seq, out_hs);
}